// round 13
// baseline (speedup 1.0000x reference)
#include <cuda_runtime.h>
#include <math.h>

#define DD 128
#define D4 32
#define MAXN 512
#define NTHR 256
#define NWARP 8
#define QCH 8                  // float4 chunks per thread per row (8192 cols)
#define GRID_P (148 * 5)

__device__ float    g_norms[16384];
__device__ unsigned g_next;

__device__ __forceinline__ void cp16(void* dst, const void* src) {
    unsigned sdst = (unsigned)__cvta_generic_to_shared(dst);
    asm volatile("cp.async.cg.shared.global [%0], [%1], 16;" :: "r"(sdst), "l"(src));
}
#define CP_COMMIT() asm volatile("cp.async.commit_group;")
#define CP_WAIT0()  asm volatile("cp.async.wait_group 0;")

// ---- norms: 4 rows per warp; resets the row queue ----
__global__ void norms_kernel(const float* __restrict__ x, int N) {
    if (blockIdx.x == 0 && threadIdx.x == 0) g_next = 0u;
    int wg   = blockIdx.x * (NTHR / 32) + (threadIdx.x >> 5);
    int lane = threadIdx.x & 31;
    int row0 = wg * 4;
    float4 v[4];
#pragma unroll
    for (int r = 0; r < 4; ++r) {
        int row = row0 + r;
        v[r] = (row < N) ? ((const float4*)x)[(size_t)row * D4 + lane]
                         : make_float4(0.f, 0.f, 0.f, 0.f);
    }
#pragma unroll
    for (int r = 0; r < 4; ++r) {
        float s = v[r].x * v[r].x + v[r].y * v[r].y + v[r].z * v[r].z + v[r].w * v[r].w;
#pragma unroll
        for (int o = 16; o > 0; o >>= 1) s += __shfl_xor_sync(0xffffffffu, s, o);
        if (lane == 0 && row0 + r < N) g_norms[row0 + r] = sqrtf(s);
    }
}

// ---- persistent kernel: whole-row cp.async prefetch overlapped with epilogue ----
__global__ void __launch_bounds__(NTHR, 5) gat_kernel(
    const float* __restrict__ x, const float* __restrict__ adj,
    const float* __restrict__ beta, float* __restrict__ out, int N)
{
    __shared__ float4 buf[QCH * NTHR];        // 32KB: one full adjacency row
    __shared__ float4 xi4[D4];
    __shared__ float4 accs4[NWARP][D4];
    __shared__ int    nidx[MAXN];
    __shared__ int    wsum[NWARP];
    __shared__ int    s_tot;
    __shared__ int    s_next;
    __shared__ float  zred[NWARP];

    const int tid  = threadIdx.x;
    const int lane = tid & 31;
    const int warp = tid >> 5;
    const float b  = beta[0];
    const int n4   = N >> 2;
    const float4* adj4 = (const float4*)adj;

    // ---- prime: pop first row, prefetch it ----
    if (tid == 0) s_next = (int)atomicAdd(&g_next, 1u);
    __syncthreads();
    int r_cur = s_next;
    if (r_cur >= N) return;
    {
        const float4* src = adj4 + (size_t)r_cur * n4;
#pragma unroll
        for (int q = 0; q < QCH; ++q) {
            int t = q * NTHR + tid;
            if (t < n4) cp16(&buf[t], src + t);
            else        buf[t] = make_float4(0.f, 0.f, 0.f, 0.f);
        }
        CP_COMMIT();
    }

    while (true) {
        if (tid == 0) s_next = (int)atomicAdd(&g_next, 1u);
        if (tid < D4) xi4[tid] = ((const float4*)x)[(size_t)r_cur * D4 + tid];

        // ---- Phase 1: mask from smem (own chunks only; wait is per-thread) ----
        CP_WAIT0();
        unsigned mask = 0u;
#pragma unroll
        for (int q = 0; q < QCH; ++q) {
            float4 a = buf[q * NTHR + tid];
            unsigned bb = (a.x != 0.f ? 1u : 0u) | (a.y != 0.f ? 2u : 0u) |
                          (a.z != 0.f ? 4u : 0u) | (a.w != 0.f ? 8u : 0u);
            mask |= bb << (q * 4);
        }
        int c = __popc(mask);

        int p = c;
#pragma unroll
        for (int o = 1; o < 32; o <<= 1) {
            int v = __shfl_up_sync(0xffffffffu, p, o);
            if (lane >= o) p += v;
        }
        if (lane == 31) wsum[warp] = p;
        __syncthreads();
        if (tid == 0) {
            int run = 0;
#pragma unroll
            for (int w = 0; w < NWARP; ++w) { int v = wsum[w]; wsum[w] = run; run += v; }
            s_tot = run;
        }
        __syncthreads();

        {
            int off = wsum[warp] + (p - c);
            unsigned msk = mask;
            while (msk) {
                int bit = __ffs(msk) - 1;
                msk &= msk - 1u;
                int col = 4 * (((bit >> 2) * NTHR) + tid) + (bit & 3);
                if (off < MAXN) nidx[off] = col;
                ++off;
            }
        }
        __syncthreads();                       // nidx + s_next visible
        const int m      = min(s_tot, (int)MAXN);
        const int r_next = s_next;

        // ---- prefetch the NEXT row; drains during the epilogue below ----
        if (r_next < N) {
            const float4* src = adj4 + (size_t)r_next * n4;
#pragma unroll
            for (int q = 0; q < QCH; ++q) {
                int t = q * NTHR + tid;
                if (t < n4) cp16(&buf[t], src + t);
            }
            CP_COMMIT();
        }

        // ---- Phase 2: fused dot/exp/accumulate, 2 nbrs/warp/round ----
        const float ni  = g_norms[r_cur];
        const float4 xi = xi4[lane];

        float4 acc = make_float4(0.f, 0.f, 0.f, 0.f);
        float  z   = 0.f;

        for (int k = warp * 2; k < m; k += 2 * NWARP) {
            const bool h1 = (k + 1 < m);
            int j0 = nidx[k];
            int j1 = h1 ? nidx[k + 1] : j0;

            float4 x0 = ((const float4*)x)[(size_t)j0 * D4 + lane];
            float4 x1 = ((const float4*)x)[(size_t)j1 * D4 + lane];
            float  n0 = g_norms[j0];
            float  n1 = g_norms[j1];

            float d0 = x0.x * xi.x + x0.y * xi.y + x0.z * xi.z + x0.w * xi.w;
            float d1 = x1.x * xi.x + x1.y * xi.y + x1.z * xi.z + x1.w * xi.w;
#pragma unroll
            for (int o = 16; o > 0; o >>= 1) {
                d0 += __shfl_xor_sync(0xffffffffu, d0, o);
                d1 += __shfl_xor_sync(0xffffffffu, d1, o);
            }

            float e0 =      __expf(b * __fdividef(d0, ni * n0 + 1e-7f));
            float e1 = h1 ? __expf(b * __fdividef(d1, ni * n1 + 1e-7f)) : 0.f;

            acc.x = fmaf(e0, x0.x, fmaf(e1, x1.x, acc.x));
            acc.y = fmaf(e0, x0.y, fmaf(e1, x1.y, acc.y));
            acc.z = fmaf(e0, x0.z, fmaf(e1, x1.z, acc.z));
            acc.w = fmaf(e0, x0.w, fmaf(e1, x1.w, acc.w));
            z += e0 + e1;
        }

        // ---- Phase 3: deterministic cross-warp combine ----
        accs4[warp][lane] = acc;
        if (lane == 0) zred[warp] = z;
        __syncthreads();

        if (tid < D4) {
            float4 s = make_float4(0.f, 0.f, 0.f, 0.f);
#pragma unroll
            for (int w = 0; w < NWARP; ++w) {
                float4 v = accs4[w][tid];
                s.x += v.x; s.y += v.y; s.z += v.z; s.w += v.w;
            }
            float Z = 0.f;
#pragma unroll
            for (int w = 0; w < NWARP; ++w) Z += zred[w];
            float invZ = 1.0f / Z;
            s.x *= invZ; s.y *= invZ; s.z *= invZ; s.w *= invZ;
            ((float4*)out)[(size_t)r_cur * D4 + tid] = s;
        }

        if (r_next >= N) break;
        r_cur = r_next;
    }
}

extern "C" void kernel_launch(void* const* d_in, const int* in_sizes, int n_in,
                              void* d_out, int out_size) {
    const float* x    = (const float*)d_in[0];
    const float* adj  = (const float*)d_in[1];
    const float* beta = (const float*)d_in[2];
    float* out = (float*)d_out;

    double asz = (double)in_sizes[1];
    int N = (int)(sqrt(asz) + 0.5);

    int rows_per_block = (NTHR / 32) * 4;
    int nb = (N + rows_per_block - 1) / rows_per_block;
    norms_kernel<<<nb, NTHR>>>(x, N);

    int grid = (N < GRID_P) ? N : GRID_P;
    gat_kernel<<<grid, NTHR>>>(x, adj, beta, out, N);
}